// round 8
// baseline (speedup 1.0000x reference)
#include <cuda_runtime.h>
#include <cuda_bf16.h>
#include <cstdint>
#include <stdint.h>
#include <math.h>

#define B_    4
#define N_    4096
#define C_    512
#define H_    16
#define D_    32
#define M_    (B_*N_)      // 16384
#define KDIM  512
#define NOUT  1024
#define NCHUNK 8
#define CHUNK (N_/NCHUNK)  // 512

// -------- scratch (device globals; no allocations allowed) --------
__device__ float  g_q[M_*C_];                      // elu(q)+1
__device__ float  g_k[M_*C_];                      // elu(k)+1
__device__ float2 g_cs[N_*256];                    // rope cos/sin table
__device__ float  g_kvp[NCHUNK*B_*H_*D_*D_];       // partial kv
__device__ float  g_ksp[NCHUNK*B_*H_*D_];          // partial k sums
__device__ float  g_kv[B_*H_*D_*D_];               // kv (scaled by 1/N)
__device__ float  g_km[B_*H_*D_];                  // kmean
// bf16x3 split operands for the tensor-core GEMM
__device__ __nv_bfloat16 g_xhi[M_*KDIM];
__device__ __nv_bfloat16 g_xlo[M_*KDIM];
__device__ __nv_bfloat16 g_wthi[NOUT*KDIM];        // W^T [n][k]
__device__ __nv_bfloat16 g_wtlo[NOUT*KDIM];

// ============================================================
// helpers (base-ISA only: ldmatrix / mma.sync / cp.async)
// ============================================================
__device__ __forceinline__ uint32_t smem_u32(const void* p) {
    uint32_t a;
    asm("{ .reg .u64 t; cvta.to.shared.u64 t, %1; cvt.u32.u64 %0, t; }"
        : "=r"(a) : "l"(p));
    return a;
}
#define CP_ASYNC16(dst, src) \
    asm volatile("cp.async.cg.shared.global [%0], [%1], 16;" :: "r"(dst), "l"(src))
#define CP_COMMIT() asm volatile("cp.async.commit_group;" ::: "memory")
#define LDSM4(r0, r1, r2, r3, addr) \
    asm volatile("ldmatrix.sync.aligned.m8n8.x4.shared.b16 {%0,%1,%2,%3}, [%4];" \
        : "=r"(r0), "=r"(r1), "=r"(r2), "=r"(r3) : "r"(addr))
#define MMA16816(d, a, b) \
    asm volatile("mma.sync.aligned.m16n8k16.row.col.f32.bf16.bf16.f32 " \
        "{%0,%1,%2,%3}, {%4,%5,%6,%7}, {%8,%9}, {%0,%1,%2,%3};" \
        : "+f"((d)[0]), "+f"((d)[1]), "+f"((d)[2]), "+f"((d)[3]) \
        : "r"((a)[0]), "r"((a)[1]), "r"((a)[2]), "r"((a)[3]), \
          "r"((b)[0]), "r"((b)[1]))

// ============================================================
// RoPE table: emulate JAX fp32 theta & ang, accurate sincos.
// ============================================================
__global__ void rope_table_k() {
    int idx = blockIdx.x * 256 + threadIdx.x;     // N_*256 entries
    int n = idx >> 8;
    int j = idx & 255;
    double theta_d = exp((double)j * (-9.210340371976184 / 256.0));
    float  theta   = (float)theta_d;
    float  ang     = (float)n * theta;            // fp32 multiply, like JAX
    double a = (double)ang;
    double kq = rint(a * 0.15915494309189535);    // 1/(2*pi)
    double r  = fma(-kq, 6.283185307179586, a);
    float s, c;
    sincosf((float)r, &s, &c);
    g_cs[idx] = make_float2(c, s);
}

// ============================================================
// bf16 hi/lo splits
// ============================================================
__global__ void split_x_k(const float* __restrict__ X) {
    int i = blockIdx.x * 256 + threadIdx.x;       // float4 index, M_*KDIM/4 total
    float4 v = ((const float4*)X)[i];
    __nv_bfloat16 h0 = __float2bfloat16(v.x), h1 = __float2bfloat16(v.y);
    __nv_bfloat16 h2 = __float2bfloat16(v.z), h3 = __float2bfloat16(v.w);
    __nv_bfloat16 l0 = __float2bfloat16(v.x - __bfloat162float(h0));
    __nv_bfloat16 l1 = __float2bfloat16(v.y - __bfloat162float(h1));
    __nv_bfloat16 l2 = __float2bfloat16(v.z - __bfloat162float(h2));
    __nv_bfloat16 l3 = __float2bfloat16(v.w - __bfloat162float(h3));
    __nv_bfloat162* ph = (__nv_bfloat162*)(g_xhi + 4 * (size_t)i);
    __nv_bfloat162* pl = (__nv_bfloat162*)(g_xlo + 4 * (size_t)i);
    ph[0] = __nv_bfloat162(h0, h1); ph[1] = __nv_bfloat162(h2, h3);
    pl[0] = __nv_bfloat162(l0, l1); pl[1] = __nv_bfloat162(l2, l3);
}

__global__ void split_wt_k(const float* __restrict__ W) {
    int i = blockIdx.x * 256 + threadIdx.x;       // NOUT*KDIM total
    int n = i >> 9, k = i & 511;
    float v = W[(size_t)k * NOUT + n];
    __nv_bfloat16 h = __float2bfloat16(v);
    g_wthi[i] = h;
    g_wtlo[i] = __float2bfloat16(v - __bfloat162float(h));
}

// ============================================================
// HMMA GEMM: qk = x @ Wqk + b via bf16x3 (3 passes folded into
// one K=1536 mainloop), fused bias + elu+1 epilogue.
// Tile 128x128xBK32, 8 warps, warp tile 64x32 (m16n8k16).
// ============================================================
#define BK 32
#define LDS_ROW 40   // halves per smem row (64B data + 16B pad): conflict-free ldmatrix

__global__ __launch_bounds__(256, 2) void gemm_hmma_k(const float* __restrict__ bias)
{
    __shared__ __align__(16) __nv_bfloat16 As[2][128 * LDS_ROW];
    __shared__ __align__(16) __nv_bfloat16 Bs[2][128 * LDS_ROW];

    int tid = threadIdx.x;
    int lane = tid & 31, wid = tid >> 5;
    int warp_m = wid & 1;         // 2 x 64 rows
    int warp_n = wid >> 1;        // 4 x 32 cols
    int mbase = blockIdx.y * 128;
    int nblk  = blockIdx.x * 128;

    uint32_t asm_b[2] = { smem_u32(As[0]), smem_u32(As[1]) };
    uint32_t bsm_b[2] = { smem_u32(Bs[0]), smem_u32(Bs[1]) };

    float acc[4][4][4];
    #pragma unroll
    for (int i = 0; i < 4; i++)
        #pragma unroll
        for (int j = 0; j < 4; j++)
            #pragma unroll
            for (int r = 0; r < 4; r++) acc[i][j][r] = 0.f;

    // per-thread load coords: 2 x 16B for A, 2 x 16B for B per chunk
    int l_row0 = tid >> 2;              // idx = tid       -> rows 0..63
    int l_row1 = (tid + 256) >> 2;      // idx = tid + 256 -> rows 64..127
    int l_cg   = tid & 3;               // 16B group within 64B row

    // 48 chunks: pass p = c>>4 in {0:(hi,hi), 1:(hi,lo), 2:(lo,hi)}
    auto prefetch = [&](int c, int buf) {
        int pass = c >> 4;
        int kc   = (c & 15) * BK;
        const __nv_bfloat16* Ap = (pass < 2) ? g_xhi : g_xlo;
        const __nv_bfloat16* Bp = (pass == 1) ? g_wtlo : g_wthi;
        uint32_t da0 = asm_b[buf] + (uint32_t)(l_row0 * LDS_ROW + l_cg * 8) * 2;
        uint32_t da1 = asm_b[buf] + (uint32_t)(l_row1 * LDS_ROW + l_cg * 8) * 2;
        uint32_t db0 = bsm_b[buf] + (uint32_t)(l_row0 * LDS_ROW + l_cg * 8) * 2;
        uint32_t db1 = bsm_b[buf] + (uint32_t)(l_row1 * LDS_ROW + l_cg * 8) * 2;
        CP_ASYNC16(da0, Ap + (size_t)(mbase + l_row0) * KDIM + kc + l_cg * 8);
        CP_ASYNC16(da1, Ap + (size_t)(mbase + l_row1) * KDIM + kc + l_cg * 8);
        CP_ASYNC16(db0, Bp + (size_t)(nblk + l_row0) * KDIM + kc + l_cg * 8);
        CP_ASYNC16(db1, Bp + (size_t)(nblk + l_row1) * KDIM + kc + l_cg * 8);
    };

    prefetch(0, 0);
    CP_COMMIT();

    for (int c = 0; c < 48; c++) {
        int buf = c & 1;
        if (c < 47) { prefetch(c + 1, buf ^ 1); CP_COMMIT(); }
        if (c < 47) asm volatile("cp.async.wait_group 1;" ::: "memory");
        else        asm volatile("cp.async.wait_group 0;" ::: "memory");
        __syncthreads();

        uint32_t ab = asm_b[buf], bb = bsm_b[buf];
        #pragma unroll
        for (int ks = 0; ks < 2; ks++) {        // two k16 sub-steps in BK=32
            uint32_t a[4][4];
            #pragma unroll
            for (int mt = 0; mt < 4; mt++) {
                int row = warp_m * 64 + mt * 16 + (lane & 15);
                int kg  = ks * 2 + (lane >> 4);
                uint32_t ad = ab + (uint32_t)(row * LDS_ROW + kg * 8) * 2;
                LDSM4(a[mt][0], a[mt][1], a[mt][2], a[mt][3], ad);
            }
            uint32_t b[4][2];
            #pragma unroll
            for (int np = 0; np < 2; np++) {    // each x4 covers two n8 tiles
                int row = warp_n * 32 + np * 16 + (lane & 7) + (lane >> 4) * 8;
                int kg  = ks * 2 + ((lane >> 3) & 1);
                uint32_t bd = bb + (uint32_t)(row * LDS_ROW + kg * 8) * 2;
                LDSM4(b[2*np][0], b[2*np][1], b[2*np+1][0], b[2*np+1][1], bd);
            }
            #pragma unroll
            for (int mt = 0; mt < 4; mt++)
                #pragma unroll
                for (int nt = 0; nt < 4; nt++)
                    MMA16816(acc[mt][nt], a[mt], b[nt]);
        }
        __syncthreads();
    }

    // epilogue: bias + elu+1 -> g_q / g_k (whole 128-col block is q or k)
    const bool isq = (nblk < C_);
    float* outp = isq ? g_q : g_k;
    int cb = nblk - (isq ? 0 : C_);
    #pragma unroll
    for (int mt = 0; mt < 4; mt++) {
        int mrow = mbase + warp_m * 64 + mt * 16 + (lane >> 2);
        #pragma unroll
        for (int nt = 0; nt < 4; nt++) {
            int ncol = warp_n * 32 + nt * 8 + (lane & 3) * 2;  // 0..127 in block
            float b0 = bias[nblk + ncol], b1 = bias[nblk + ncol + 1];
            float v0 = acc[mt][nt][0] + b0;
            float v1 = acc[mt][nt][1] + b1;
            float v2 = acc[mt][nt][2] + b0;
            float v3 = acc[mt][nt][3] + b1;
            float2 o01, o23;
            o01.x = v0 > 0.f ? v0 + 1.f : expf(v0);
            o01.y = v1 > 0.f ? v1 + 1.f : expf(v1);
            o23.x = v2 > 0.f ? v2 + 1.f : expf(v2);
            o23.y = v3 > 0.f ? v3 + 1.f : expf(v3);
            *(float2*)(outp + (size_t)mrow * C_ + cb + ncol) = o01;
            *(float2*)(outp + (size_t)(mrow + 8) * C_ + cb + ncol) = o23;
        }
    }
}

// ============================================================
// kv partials: per (b,h,chunk): kv += k_rope^T v ; ksum += k
// ============================================================
__global__ __launch_bounds__(256) void kv_k(const float* __restrict__ X) {
    int bh = blockIdx.x;              // B_*H_
    int b  = bh >> 4;
    int h  = bh & 15;
    int chunk = blockIdx.y;
    int tid = threadIdx.x;
    int p  = tid & 15;                // pair within head
    int r0 = tid >> 4;                // 0..15

    __shared__ __align__(16) float kr[64][32];
    __shared__ __align__(16) float vs[64][32];
    __shared__ float sred[16][32];

    float4 acc = make_float4(0.f, 0.f, 0.f, 0.f);
    float se = 0.f, so = 0.f;
    int d  = tid >> 3;                // 0..31
    int e0 = (tid & 7) * 4;

    for (int sub = 0; sub < CHUNK; sub += 64) {
        int nb = chunk * CHUNK + sub;
        #pragma unroll
        for (int s = 0; s < 4; s++) {
            int r = r0 + s * 16;
            int n = nb + r;
            size_t base = (size_t)(b * N_ + n) * C_ + h * 32 + 2 * p;
            float2 kp = *(const float2*)(g_k + base);
            float2 cs = g_cs[n * 256 + h * 16 + p];
            se += kp.x; so += kp.y;
            float2 krr = make_float2(kp.x * cs.x - kp.y * cs.y,
                                     kp.x * cs.y + kp.y * cs.x);
            *(float2*)(&kr[r][2 * p]) = krr;
            *(float2*)(&vs[r][2 * p]) = *(const float2*)(X + base);
        }
        __syncthreads();
        #pragma unroll 8
        for (int r = 0; r < 64; r++) {
            float a = kr[r][d];
            float4 v = *(const float4*)(&vs[r][e0]);
            acc.x += a * v.x; acc.y += a * v.y;
            acc.z += a * v.z; acc.w += a * v.w;
        }
        __syncthreads();
    }

    float* kvp = g_kvp + ((size_t)chunk * B_ * H_ + bh) * 1024;
    *(float4*)(kvp + d * 32 + e0) = acc;

    sred[r0][2 * p]     = se;
    sred[r0][2 * p + 1] = so;
    __syncthreads();
    if (tid < 32) {
        float s = 0.f;
        #pragma unroll
        for (int i = 0; i < 16; i++) s += sred[i][tid];
        g_ksp[((size_t)chunk * B_ * H_ + bh) * 32 + tid] = s;
    }
}

// ============================================================
// deterministic reduce of partials, scale by 1/N
// ============================================================
__global__ void kvreduce_k() {
    int i = blockIdx.x * 256 + threadIdx.x;  // B*H*1024 = 65536
    float s = 0.f;
    #pragma unroll
    for (int c = 0; c < NCHUNK; c++) s += g_kvp[(size_t)c * B_ * H_ * 1024 + i];
    g_kv[i] = s * (1.f / N_);
    if (i < B_ * H_ * 32) {
        float t = 0.f;
        #pragma unroll
        for (int c = 0; c < NCHUNK; c++) t += g_ksp[(size_t)c * B_ * H_ * 32 + i];
        g_km[i] = t * (1.f / N_);
    }
}

// ============================================================
// out = (q_rope @ kv) * z + lepe
// ============================================================
__global__ __launch_bounds__(256) void out_k(
    const float* __restrict__ X, const float* __restrict__ lw,
    const float* __restrict__ lb, float* __restrict__ out)
{
    int tile = blockIdx.x;    // N_/32
    int b    = blockIdx.y;
    int half = blockIdx.z;    // 0 or 1 (8 heads each)
    int tid  = threadIdx.x;

    __shared__ __align__(16) float kvs[8 * 1024];   // 32 KB
    __shared__ float kms[256];
    __shared__ float qs[256];
    __shared__ float qrs[256];
    __shared__ float zs[8];

    const float* kvsrc = g_kv + ((size_t)b * 16 + half * 8) * 1024;
    for (int i = tid; i < 8192; i += 256) kvs[i] = kvsrc[i];
    if (tid < 256) kms[tid] = g_km[b * 512 + half * 256 + tid];
    __syncthreads();

    int hl = tid >> 5;        // local head 0..7
    int e  = tid & 31;
    const float* kvh = kvs + hl * 1024;

    for (int r = 0; r < 32; r++) {
        int n = tile * 32 + r;
        size_t row = (size_t)(b * N_ + n) * C_;

        if (tid < 128) {
            float2 qp = *(const float2*)(g_q + row + half * 256 + 2 * tid);
            float2 cs = g_cs[n * 256 + half * 128 + tid];
            qs[2 * tid]      = qp.x;
            qs[2 * tid + 1]  = qp.y;
            qrs[2 * tid]     = qp.x * cs.x - qp.y * cs.y;
            qrs[2 * tid + 1] = qp.x * cs.y + qp.y * cs.x;
        }
        __syncthreads();

        if (tid < 8) {
            float dot = 0.f;
            #pragma unroll
            for (int dd = 0; dd < 32; dd++) dot += qs[tid * 32 + dd] * kms[tid * 32 + dd];
            zs[tid] = 1.f / (dot + 1e-6f);
        }
        __syncthreads();

        float a0 = 0.f;
        const float* qh = qrs + hl * 32;
        #pragma unroll
        for (int dd = 0; dd < 32; dd++)
            a0 += qh[dd] * kvh[dd * 32 + e];
        a0 *= zs[hl];

        int c = half * 256 + tid;   // global channel
        float xc = X[row + c];
        float xm = (n > 0)      ? X[row - C_ + c] : 0.f;
        float xp = (n < N_ - 1) ? X[row + C_ + c] : 0.f;
        float l = xm * lw[c * 3 + 0] + xc * lw[c * 3 + 1] + xp * lw[c * 3 + 2] + lb[c];

        out[row + c] = a0 + l;
        __syncthreads();
    }
}

// ============================================================
extern "C" void kernel_launch(void* const* d_in, const int* in_sizes, int n_in,
                              void* d_out, int out_size) {
    const float* x   = (const float*)d_in[0];
    const float* Wqk = (const float*)d_in[1];
    const float* bqk = (const float*)d_in[2];
    const float* lw  = (const float*)d_in[3];
    const float* lb  = (const float*)d_in[4];
    float* out = (float*)d_out;

    rope_table_k<<<N_ * 256 / 256, 256>>>();
    split_x_k<<<M_ * KDIM / 4 / 256, 256>>>(x);
    split_wt_k<<<NOUT * KDIM / 256, 256>>>(Wqk);
    gemm_hmma_k<<<dim3(NOUT / 128, M_ / 128), 256>>>(bqk);
    kv_k<<<dim3(B_ * H_, NCHUNK), 256>>>(x);
    kvreduce_k<<<B_ * H_ * 1024 / 256, 256>>>();
    out_k<<<dim3(N_ / 32, B_, 2), 256>>>(x, lw, lb, out);
}

// round 10
// speedup vs baseline: 2.0620x; 2.0620x over previous
#include <cuda_runtime.h>
#include <cuda_bf16.h>
#include <cstdint>
#include <stdint.h>
#include <math.h>

#define B_    4
#define N_    4096
#define C_    512
#define H_    16
#define D_    32
#define M_    (B_*N_)      // 16384
#define KDIM  512
#define NOUT  1024
#define NCHUNK 8
#define CHUNK (N_/NCHUNK)  // 512

// -------- scratch (device globals; no allocations allowed) --------
__device__ float  g_q[M_*C_];                      // elu(q)+1
__device__ float  g_k[M_*C_];                      // elu(k)+1
__device__ float2 g_cs[N_*256];                    // rope cos/sin table
__device__ float  g_kvp[NCHUNK*B_*H_*D_*D_];       // partial kv
__device__ float  g_ksp[NCHUNK*B_*H_*D_];          // partial k sums
__device__ float  g_kv[B_*H_*D_*D_];               // kv (scaled by 1/N)
__device__ float  g_km[B_*H_*D_];                  // kmean
// bf16x3 split operands for the tensor-core GEMM
__device__ __nv_bfloat16 g_xhi[M_*KDIM];
__device__ __nv_bfloat16 g_xlo[M_*KDIM];
__device__ __nv_bfloat16 g_wthi[NOUT*KDIM];        // W^T [n][k]
__device__ __nv_bfloat16 g_wtlo[NOUT*KDIM];

// ============================================================
// helpers (base-ISA only: ldmatrix / mma.sync / cp.async)
// ============================================================
__device__ __forceinline__ uint32_t smem_u32(const void* p) {
    uint32_t a;
    asm("{ .reg .u64 t; cvta.to.shared.u64 t, %1; cvt.u32.u64 %0, t; }"
        : "=r"(a) : "l"(p));
    return a;
}
#define CP_ASYNC16(dst, src) \
    asm volatile("cp.async.cg.shared.global [%0], [%1], 16;" :: "r"(dst), "l"(src))
#define CP_COMMIT() asm volatile("cp.async.commit_group;" ::: "memory")
#define LDSM4(r0, r1, r2, r3, addr) \
    asm volatile("ldmatrix.sync.aligned.m8n8.x4.shared.b16 {%0,%1,%2,%3}, [%4];" \
        : "=r"(r0), "=r"(r1), "=r"(r2), "=r"(r3) : "r"(addr))
#define MMA16816(d, a, b) \
    asm volatile("mma.sync.aligned.m16n8k16.row.col.f32.bf16.bf16.f32 " \
        "{%0,%1,%2,%3}, {%4,%5,%6,%7}, {%8,%9}, {%0,%1,%2,%3};" \
        : "+f"((d)[0]), "+f"((d)[1]), "+f"((d)[2]), "+f"((d)[3]) \
        : "r"((a)[0]), "r"((a)[1]), "r"((a)[2]), "r"((a)[3]), \
          "r"((b)[0]), "r"((b)[1]))

// ============================================================
// RoPE table: emulate JAX fp32 theta & ang, accurate sincos.
// ============================================================
__global__ void rope_table_k() {
    int idx = blockIdx.x * 256 + threadIdx.x;     // N_*256 entries
    int n = idx >> 8;
    int j = idx & 255;
    double theta_d = exp((double)j * (-9.210340371976184 / 256.0));
    float  theta   = (float)theta_d;
    float  ang     = (float)n * theta;            // fp32 multiply, like JAX
    double a = (double)ang;
    double kq = rint(a * 0.15915494309189535);    // 1/(2*pi)
    double r  = fma(-kq, 6.283185307179586, a);
    float s, c;
    sincosf((float)r, &s, &c);
    g_cs[idx] = make_float2(c, s);
}

// ============================================================
// bf16 hi/lo splits
// ============================================================
__global__ void split_x_k(const float* __restrict__ X) {
    int i = blockIdx.x * 256 + threadIdx.x;       // float4 index, M_*KDIM/4 total
    float4 v = ((const float4*)X)[i];
    __nv_bfloat16 h0 = __float2bfloat16(v.x), h1 = __float2bfloat16(v.y);
    __nv_bfloat16 h2 = __float2bfloat16(v.z), h3 = __float2bfloat16(v.w);
    __nv_bfloat16 l0 = __float2bfloat16(v.x - __bfloat162float(h0));
    __nv_bfloat16 l1 = __float2bfloat16(v.y - __bfloat162float(h1));
    __nv_bfloat16 l2 = __float2bfloat16(v.z - __bfloat162float(h2));
    __nv_bfloat16 l3 = __float2bfloat16(v.w - __bfloat162float(h3));
    __nv_bfloat162* ph = (__nv_bfloat162*)(g_xhi + 4 * (size_t)i);
    __nv_bfloat162* pl = (__nv_bfloat162*)(g_xlo + 4 * (size_t)i);
    ph[0] = __nv_bfloat162(h0, h1); ph[1] = __nv_bfloat162(h2, h3);
    pl[0] = __nv_bfloat162(l0, l1); pl[1] = __nv_bfloat162(l2, l3);
}

__global__ void split_wt_k(const float* __restrict__ W) {
    int i = blockIdx.x * 256 + threadIdx.x;       // NOUT*KDIM total
    int n = i >> 9, k = i & 511;
    float v = W[(size_t)k * NOUT + n];
    __nv_bfloat16 h = __float2bfloat16(v);
    g_wthi[i] = h;
    g_wtlo[i] = __float2bfloat16(v - __bfloat162float(h));
}

// ============================================================
// HMMA GEMM: qk = x @ Wqk + b via bf16x3 (K_eff = 1536),
// 3-stage cp.async pipeline, BK=64, one barrier per chunk.
// Tile 128x128, 8 warps, warp tile 64x32 (m16n8k16).
// ============================================================
#define BK      64
#define LDS_ROW 72                  // 64 halves + 8 pad: conflict-free ldmatrix
#define TILE_B  (128 * LDS_ROW * 2) // 18432 bytes per operand tile
#define STAGE_B (2 * TILE_B)        // 36864 per stage
#define GEMM_SMEM (3 * STAGE_B)     // 110592

__global__ __launch_bounds__(256, 2) void gemm_hmma_k(const float* __restrict__ bias)
{
    extern __shared__ __align__(16) char sm[];
    uint32_t smb = smem_u32(sm);

    int tid = threadIdx.x;
    int lane = tid & 31, wid = tid >> 5;
    int warp_m = wid & 1;         // 2 x 64 rows
    int warp_n = wid >> 1;        // 4 x 32 cols
    int mbase = blockIdx.y * 128;
    int nblk  = blockIdx.x * 128;

    float acc[4][4][4];
    #pragma unroll
    for (int i = 0; i < 4; i++)
        #pragma unroll
        for (int j = 0; j < 4; j++)
            #pragma unroll
            for (int r = 0; r < 4; r++) acc[i][j][r] = 0.f;

    // 24 chunks of BK=64; pass = c>>3 in {0:(hi,hi), 1:(hi,lo), 2:(lo,hi)}
    auto prefetch = [&](int c, int s) {
        int pass = c >> 3;
        int kc   = (c & 7) * BK;
        const __nv_bfloat16* Ap = (pass < 2) ? g_xhi : g_xlo;
        const __nv_bfloat16* Bp = (pass == 1) ? g_wtlo : g_wthi;
        uint32_t ab = smb + s * STAGE_B;
        uint32_t bb = ab + TILE_B;
        #pragma unroll
        for (int t = 0; t < 4; t++) {
            int idx = tid + t * 256;
            int row = idx >> 3, cg = idx & 7;
            CP_ASYNC16(ab + (uint32_t)(row * LDS_ROW + cg * 8) * 2,
                       Ap + (size_t)(mbase + row) * KDIM + kc + cg * 8);
        }
        #pragma unroll
        for (int t = 0; t < 4; t++) {
            int idx = tid + t * 256;
            int row = idx >> 3, cg = idx & 7;
            CP_ASYNC16(bb + (uint32_t)(row * LDS_ROW + cg * 8) * 2,
                       Bp + (size_t)(nblk + row) * KDIM + kc + cg * 8);
        }
    };

    prefetch(0, 0); CP_COMMIT();
    prefetch(1, 1); CP_COMMIT();

    int s = 0;
    for (int c = 0; c < 24; c++) {
        if (c < 23) asm volatile("cp.async.wait_group 1;" ::: "memory");
        else        asm volatile("cp.async.wait_group 0;" ::: "memory");
        __syncthreads();
        if (c + 2 < 24) {
            int sn = s + 2; if (sn >= 3) sn -= 3;
            prefetch(c + 2, sn);
            CP_COMMIT();
        }

        uint32_t ab = smb + s * STAGE_B;
        uint32_t bb = ab + TILE_B;
        #pragma unroll
        for (int ks = 0; ks < 4; ks++) {        // four k16 sub-steps in BK=64
            uint32_t a[4][4];
            #pragma unroll
            for (int mt = 0; mt < 4; mt++) {
                int row = warp_m * 64 + mt * 16 + (lane & 15);
                int kg  = ks * 2 + (lane >> 4);
                uint32_t ad = ab + (uint32_t)(row * LDS_ROW + kg * 8) * 2;
                LDSM4(a[mt][0], a[mt][1], a[mt][2], a[mt][3], ad);
            }
            uint32_t b[4][2];
            #pragma unroll
            for (int np = 0; np < 2; np++) {    // each x4 covers two n8 tiles
                int row = warp_n * 32 + np * 16 + (lane & 7) + (lane >> 4) * 8;
                int kg  = ks * 2 + ((lane >> 3) & 1);
                uint32_t bd = bb + (uint32_t)(row * LDS_ROW + kg * 8) * 2;
                LDSM4(b[2*np][0], b[2*np][1], b[2*np+1][0], b[2*np+1][1], bd);
            }
            #pragma unroll
            for (int mt = 0; mt < 4; mt++)
                #pragma unroll
                for (int nt = 0; nt < 4; nt++)
                    MMA16816(acc[mt][nt], a[mt], b[nt]);
        }
        if (++s >= 3) s -= 3;
    }

    // epilogue: bias + elu+1 -> g_q / g_k (whole 128-col block is q or k)
    const bool isq = (nblk < C_);
    float* outp = isq ? g_q : g_k;
    int cb = nblk - (isq ? 0 : C_);
    #pragma unroll
    for (int mt = 0; mt < 4; mt++) {
        int mrow = mbase + warp_m * 64 + mt * 16 + (lane >> 2);
        #pragma unroll
        for (int nt = 0; nt < 4; nt++) {
            int ncol = warp_n * 32 + nt * 8 + (lane & 3) * 2;  // 0..127 in block
            float b0 = bias[nblk + ncol], b1 = bias[nblk + ncol + 1];
            float v0 = acc[mt][nt][0] + b0;
            float v1 = acc[mt][nt][1] + b1;
            float v2 = acc[mt][nt][2] + b0;
            float v3 = acc[mt][nt][3] + b1;
            float2 o01, o23;
            o01.x = v0 > 0.f ? v0 + 1.f : expf(v0);
            o01.y = v1 > 0.f ? v1 + 1.f : expf(v1);
            o23.x = v2 > 0.f ? v2 + 1.f : expf(v2);
            o23.y = v3 > 0.f ? v3 + 1.f : expf(v3);
            *(float2*)(outp + (size_t)mrow * C_ + cb + ncol) = o01;
            *(float2*)(outp + (size_t)(mrow + 8) * C_ + cb + ncol) = o23;
        }
    }
}

// ============================================================
// kv partials: per (b,h,chunk): kv += k_rope^T v ; ksum += k
// ============================================================
__global__ __launch_bounds__(256) void kv_k(const float* __restrict__ X) {
    int bh = blockIdx.x;              // B_*H_
    int b  = bh >> 4;
    int h  = bh & 15;
    int chunk = blockIdx.y;
    int tid = threadIdx.x;
    int p  = tid & 15;                // pair within head
    int r0 = tid >> 4;                // 0..15

    __shared__ __align__(16) float kr[64][32];
    __shared__ __align__(16) float vs[64][32];
    __shared__ float sred[16][32];

    float4 acc = make_float4(0.f, 0.f, 0.f, 0.f);
    float se = 0.f, so = 0.f;
    int d  = tid >> 3;                // 0..31
    int e0 = (tid & 7) * 4;

    for (int sub = 0; sub < CHUNK; sub += 64) {
        int nb = chunk * CHUNK + sub;
        #pragma unroll
        for (int s = 0; s < 4; s++) {
            int r = r0 + s * 16;
            int n = nb + r;
            size_t base = (size_t)(b * N_ + n) * C_ + h * 32 + 2 * p;
            float2 kp = *(const float2*)(g_k + base);
            float2 cs = g_cs[n * 256 + h * 16 + p];
            se += kp.x; so += kp.y;
            float2 krr = make_float2(kp.x * cs.x - kp.y * cs.y,
                                     kp.x * cs.y + kp.y * cs.x);
            *(float2*)(&kr[r][2 * p]) = krr;
            *(float2*)(&vs[r][2 * p]) = *(const float2*)(X + base);
        }
        __syncthreads();
        #pragma unroll 8
        for (int r = 0; r < 64; r++) {
            float a = kr[r][d];
            float4 v = *(const float4*)(&vs[r][e0]);
            acc.x += a * v.x; acc.y += a * v.y;
            acc.z += a * v.z; acc.w += a * v.w;
        }
        __syncthreads();
    }

    float* kvp = g_kvp + ((size_t)chunk * B_ * H_ + bh) * 1024;
    *(float4*)(kvp + d * 32 + e0) = acc;

    sred[r0][2 * p]     = se;
    sred[r0][2 * p + 1] = so;
    __syncthreads();
    if (tid < 32) {
        float s = 0.f;
        #pragma unroll
        for (int i = 0; i < 16; i++) s += sred[i][tid];
        g_ksp[((size_t)chunk * B_ * H_ + bh) * 32 + tid] = s;
    }
}

// ============================================================
// deterministic reduce of partials, scale by 1/N
// ============================================================
__global__ void kvreduce_k() {
    int i = blockIdx.x * 256 + threadIdx.x;  // B*H*1024 = 65536
    float s = 0.f;
    #pragma unroll
    for (int c = 0; c < NCHUNK; c++) s += g_kvp[(size_t)c * B_ * H_ * 1024 + i];
    g_kv[i] = s * (1.f / N_);
    if (i < B_ * H_ * 32) {
        float t = 0.f;
        #pragma unroll
        for (int c = 0; c < NCHUNK; c++) t += g_ksp[(size_t)c * B_ * H_ * 32 + i];
        g_km[i] = t * (1.f / N_);
    }
}

// ============================================================
// out = (q_rope @ kv) * z + lepe  — 3 barriers per 32-row tile,
// kv in registers (fixed head/channel per thread), parallel z.
// ============================================================
__global__ __launch_bounds__(256) void out_k(
    const float* __restrict__ X, const float* __restrict__ lw,
    const float* __restrict__ lb, float* __restrict__ out)
{
    int tile = blockIdx.x;    // N_/32
    int b    = blockIdx.y;
    int half = blockIdx.z;    // 0 or 1 (8 heads each)
    int tid  = threadIdx.x;

    __shared__ float qs[32][257];    // unrotated q (this half)
    __shared__ float qrs[32][257];   // rope(q)
    __shared__ float kms[256];
    __shared__ float zs[32][8];

    int hl = tid >> 5;        // local head 0..7
    int e  = tid & 31;
    int head = half * 8 + hl;
    int c = half * 256 + tid; // global channel

    // kv column for this (head, e) into registers
    float kvr[32];
    const float* kvp = g_kv + ((size_t)(b * 16 + head)) * 1024 + e;
    #pragma unroll
    for (int dd = 0; dd < 32; dd++) kvr[dd] = kvp[dd * 32];

    kms[tid] = g_km[b * 512 + half * 256 + tid];
    float w0 = lw[c * 3 + 0], w1 = lw[c * 3 + 1], w2 = lw[c * 3 + 2];
    float lbc = lb[c];

    // phase 1: load 32 q rows (this half), rope into smem
    int pr = tid & 127;       // pair index within half (0..127)
    int rh = tid >> 7;        // 0/1
    #pragma unroll 4
    for (int i = 0; i < 16; i++) {
        int r = i * 2 + rh;
        int n = tile * 32 + r;
        float2 qp = *(const float2*)(g_q + (size_t)(b * N_ + n) * C_ + half * 256 + 2 * pr);
        float2 cs = g_cs[n * 256 + half * 128 + pr];
        qs[r][2 * pr]      = qp.x;
        qs[r][2 * pr + 1]  = qp.y;
        qrs[r][2 * pr]     = qp.x * cs.x - qp.y * cs.y;
        qrs[r][2 * pr + 1] = qp.x * cs.y + qp.y * cs.x;
    }
    __syncthreads();

    // phase 2: z for all (row, head) in parallel; lanes map rows (conflict-free)
    {
        int h2 = tid >> 5, r2 = tid & 31;
        float dot = 0.f;
        #pragma unroll
        for (int dd = 0; dd < 32; dd++) dot += qs[r2][h2 * 32 + dd] * kms[h2 * 32 + dd];
        zs[r2][h2] = 1.f / (dot + 1e-6f);
    }
    __syncthreads();

    // phase 3: outputs + fused LePE conv
    for (int r = 0; r < 32; r++) {
        int n = tile * 32 + r;
        size_t row = (size_t)(b * N_ + n) * C_;
        float a0 = 0.f;
        #pragma unroll
        for (int dd = 0; dd < 32; dd++)
            a0 += qrs[r][hl * 32 + dd] * kvr[dd];
        a0 *= zs[r][hl];

        float xc = X[row + c];
        float xm = (n > 0)      ? X[row - C_ + c] : 0.f;
        float xp = (n < N_ - 1) ? X[row + C_ + c] : 0.f;
        out[row + c] = a0 + xm * w0 + xc * w1 + xp * w2 + lbc;
    }
}

// ============================================================
extern "C" void kernel_launch(void* const* d_in, const int* in_sizes, int n_in,
                              void* d_out, int out_size) {
    const float* x   = (const float*)d_in[0];
    const float* Wqk = (const float*)d_in[1];
    const float* bqk = (const float*)d_in[2];
    const float* lw  = (const float*)d_in[3];
    const float* lb  = (const float*)d_in[4];
    float* out = (float*)d_out;

    cudaFuncSetAttribute(gemm_hmma_k, cudaFuncAttributeMaxDynamicSharedMemorySize, GEMM_SMEM);

    rope_table_k<<<N_ * 256 / 256, 256>>>();
    split_x_k<<<M_ * KDIM / 4 / 256, 256>>>(x);
    split_wt_k<<<NOUT * KDIM / 256, 256>>>(Wqk);
    gemm_hmma_k<<<dim3(NOUT / 128, M_ / 128), 256, GEMM_SMEM>>>(bqk);
    kv_k<<<dim3(B_ * H_, NCHUNK), 256>>>(x);
    kvreduce_k<<<B_ * H_ * 1024 / 256, 256>>>();
    out_k<<<dim3(N_ / 32, B_, 2), 256>>>(x, lw, lb, out);
}